// round 1
// baseline (speedup 1.0000x reference)
#include <cuda_runtime.h>
#include <math.h>

// Problem constants
#define BB 8
#define SS 4096
#define DM 1024
#define NN 256
#define MM (BB * SS)          // 32768 rows

// Scratch (device globals; no allocation allowed)
__device__ float g_alpha[MM * NN];   // sigmoid(u Wa^T + ba)   (B,S,N)
__device__ float g_bu[MM * NN];      // u Wb^T + bb            (B,S,N)
__device__ float g_xs[MM * NN];      // scan output            (B,S,N)

// ---------------------------------------------------------------------------
// Tiled fp32 SGEMM core: 64x64 block tile, BK=16, 256 threads, 4x4 microtile.
// Both operands are "NT": row-major with K contiguous.
// ---------------------------------------------------------------------------

// Kernel 1: O(m, n) for n in [0,512): cols 0..255 -> sigmoid(u.Wa^T + ba) -> g_alpha
//                                     cols 256..511 -> u.Wb^T + bb        -> g_bu
__global__ void __launch_bounds__(256)
gemm1_kernel(const float* __restrict__ u,
             const float* __restrict__ Wa, const float* __restrict__ ba,
             const float* __restrict__ Wb, const float* __restrict__ bb)
{
    __shared__ float As[16][68];
    __shared__ float Bs[16][68];

    const int bm = blockIdx.x * 64;
    const int bn = blockIdx.y * 64;      // 0..448, block entirely inside Wa or Wb half

    const bool is_a = (bn < NN);
    const float* W    = is_a ? (Wa + (size_t)bn * DM) : (Wb + (size_t)(bn - NN) * DM);
    const float* bias = is_a ? (ba + bn) : (bb + (bn - NN));

    const int tid = threadIdx.x;
    const int lr = tid >> 2;             // 0..63 load row
    const int lc = (tid & 3) * 4;        // 0,4,8,12 load col
    const int ty = tid >> 4;             // 0..15
    const int tx = tid & 15;             // 0..15

    const float* Ag = u + (size_t)(bm + lr) * DM + lc;
    const float* Bg = W + (size_t)lr * DM + lc;

    float acc[4][4];
    #pragma unroll
    for (int i = 0; i < 4; i++)
        #pragma unroll
        for (int j = 0; j < 4; j++) acc[i][j] = 0.f;

    for (int k0 = 0; k0 < DM; k0 += 16) {
        float4 av = *(const float4*)(Ag + k0);
        float4 bv = *(const float4*)(Bg + k0);
        As[lc + 0][lr] = av.x; As[lc + 1][lr] = av.y;
        As[lc + 2][lr] = av.z; As[lc + 3][lr] = av.w;
        Bs[lc + 0][lr] = bv.x; Bs[lc + 1][lr] = bv.y;
        Bs[lc + 2][lr] = bv.z; Bs[lc + 3][lr] = bv.w;
        __syncthreads();

        #pragma unroll
        for (int k = 0; k < 16; k++) {
            float a[4], b[4];
            #pragma unroll
            for (int i = 0; i < 4; i++) a[i] = As[k][ty * 4 + i];
            #pragma unroll
            for (int j = 0; j < 4; j++) b[j] = Bs[k][tx * 4 + j];
            #pragma unroll
            for (int i = 0; i < 4; i++)
                #pragma unroll
                for (int j = 0; j < 4; j++)
                    acc[i][j] = fmaf(a[i], b[j], acc[i][j]);
        }
        __syncthreads();
    }

    // Epilogue: bias (+ sigmoid for the alpha half), write to scratch
    #pragma unroll
    for (int i = 0; i < 4; i++) {
        const int m = bm + ty * 4 + i;
        #pragma unroll
        for (int j = 0; j < 4; j++) {
            const int ncol = tx * 4 + j;                 // col within block
            float v = acc[i][j] + bias[ncol];
            if (is_a) {
                v = 1.0f / (1.0f + __expf(-v));
                g_alpha[(size_t)m * NN + bn + ncol] = v;
            } else {
                g_bu[(size_t)m * NN + (bn - NN) + ncol] = v;
            }
        }
    }
}

// ---------------------------------------------------------------------------
// Kernel 2: sequential scan over S for each (b, n). 8 blocks x 256 threads.
// Software-pipelined: 16-step prefetch double-buffer so loads (independent of
// the recurrence) overlap the serial FMA chain.
// ---------------------------------------------------------------------------
__global__ void __launch_bounds__(256)
scan_kernel()
{
    const int b = blockIdx.x;
    const int n = threadIdx.x;
    const size_t base = (size_t)b * SS * NN + n;
    const float* A  = g_alpha + base;
    const float* Bv = g_bu + base;
    float*       X  = g_xs + base;

    const int PF = 16;
    float a0[PF], b0[PF];
    #pragma unroll
    for (int i = 0; i < PF; i++) {
        a0[i] = A[(size_t)i * NN];
        b0[i] = Bv[(size_t)i * NN];
    }

    float x = 0.0f;
    for (int s0 = 0; s0 < SS; s0 += PF) {
        float a1[PF], b1[PF];
        const int nxt = s0 + PF;
        if (nxt < SS) {
            #pragma unroll
            for (int i = 0; i < PF; i++) {
                a1[i] = A[(size_t)(nxt + i) * NN];
                b1[i] = Bv[(size_t)(nxt + i) * NN];
            }
        } else {
            #pragma unroll
            for (int i = 0; i < PF; i++) { a1[i] = 0.f; b1[i] = 0.f; }
        }
        #pragma unroll
        for (int i = 0; i < PF; i++) {
            x = fmaf(a0[i], x, b0[i]);
            X[(size_t)(s0 + i) * NN] = x;
        }
        #pragma unroll
        for (int i = 0; i < PF; i++) { a0[i] = a1[i]; b0[i] = b1[i]; }
    }
}

// ---------------------------------------------------------------------------
// Kernel 3: y = xs.C^T + u.Dm^T   (single GEMM over concatenated K = 256+1024)
//   k in [0,256):    X part = g_xs (ld 256),  W part = C  (1024x256, ld 256)
//   k in [256,1280): X part = u    (ld 1024), W part = Dm (1024x1024, ld 1024)
// ---------------------------------------------------------------------------
__global__ void __launch_bounds__(256)
gemm2_kernel(const float* __restrict__ u,
             const float* __restrict__ C,
             const float* __restrict__ Dmat,
             float* __restrict__ out)
{
    __shared__ float As[16][68];
    __shared__ float Bs[16][68];

    const int bm = blockIdx.x * 64;
    const int bn = blockIdx.y * 64;      // output d dimension, 0..960

    const int tid = threadIdx.x;
    const int lr = tid >> 2;
    const int lc = (tid & 3) * 4;
    const int ty = tid >> 4;
    const int tx = tid & 15;

    float acc[4][4];
    #pragma unroll
    for (int i = 0; i < 4; i++)
        #pragma unroll
        for (int j = 0; j < 4; j++) acc[i][j] = 0.f;

    for (int k0 = 0; k0 < NN + DM; k0 += 16) {
        float4 av, bv;
        if (k0 < NN) {
            av = *(const float4*)(g_xs + (size_t)(bm + lr) * NN + k0 + lc);
            bv = *(const float4*)(C    + (size_t)(bn + lr) * NN + k0 + lc);
        } else {
            const int kk = k0 - NN;
            av = *(const float4*)(u    + (size_t)(bm + lr) * DM + kk + lc);
            bv = *(const float4*)(Dmat + (size_t)(bn + lr) * DM + kk + lc);
        }
        As[lc + 0][lr] = av.x; As[lc + 1][lr] = av.y;
        As[lc + 2][lr] = av.z; As[lc + 3][lr] = av.w;
        Bs[lc + 0][lr] = bv.x; Bs[lc + 1][lr] = bv.y;
        Bs[lc + 2][lr] = bv.z; Bs[lc + 3][lr] = bv.w;
        __syncthreads();

        #pragma unroll
        for (int k = 0; k < 16; k++) {
            float a[4], b[4];
            #pragma unroll
            for (int i = 0; i < 4; i++) a[i] = As[k][ty * 4 + i];
            #pragma unroll
            for (int j = 0; j < 4; j++) b[j] = Bs[k][tx * 4 + j];
            #pragma unroll
            for (int i = 0; i < 4; i++)
                #pragma unroll
                for (int j = 0; j < 4; j++)
                    acc[i][j] = fmaf(a[i], b[j], acc[i][j]);
        }
        __syncthreads();
    }

    #pragma unroll
    for (int i = 0; i < 4; i++) {
        const int m = bm + ty * 4 + i;
        #pragma unroll
        for (int j = 0; j < 4; j++) {
            const int d = bn + tx * 4 + j;
            out[(size_t)m * DM + d] = acc[i][j];
        }
    }
}

// ---------------------------------------------------------------------------
extern "C" void kernel_launch(void* const* d_in, const int* in_sizes, int n_in,
                              void* d_out, int out_size)
{
    const float* u  = (const float*)d_in[0];
    const float* Wa = (const float*)d_in[1];
    const float* ba = (const float*)d_in[2];
    const float* Wb = (const float*)d_in[3];
    const float* bb = (const float*)d_in[4];
    const float* C  = (const float*)d_in[5];
    const float* Dm = (const float*)d_in[6];
    float* out = (float*)d_out;

    {
        dim3 grid(MM / 64, (2 * NN) / 64);   // 512 x 8
        gemm1_kernel<<<grid, 256>>>(u, Wa, ba, Wb, bb);
    }
    {
        scan_kernel<<<BB, NN>>>();           // 8 blocks x 256 threads
    }
    {
        dim3 grid(MM / 64, DM / 64);         // 512 x 16
        gemm2_kernel<<<grid, 256>>>(u, C, Dm, out);
    }
}

// round 5
// speedup vs baseline: 2.4012x; 2.4012x over previous
#include <cuda_runtime.h>
#include <cuda_bf16.h>
#include <cstdint>

#define BB 8
#define SS 4096
#define DM 1024
#define NN 256
#define MM (BB*SS)   // 32768

// ---------------------------------------------------------------------------
// Scratch (device globals; allocation is forbidden)
// ---------------------------------------------------------------------------
__device__ float g_alpha[(size_t)MM * NN];
__device__ float g_bu[(size_t)MM * NN];
__device__ __nv_bfloat16 g_uhi[(size_t)MM * DM];
__device__ __nv_bfloat16 g_ulo[(size_t)MM * DM];
__device__ __nv_bfloat16 g_xhi[(size_t)MM * NN];
__device__ __nv_bfloat16 g_xlo[(size_t)MM * NN];
__device__ __nv_bfloat16 g_Whi[512 * DM];
__device__ __nv_bfloat16 g_Wlo[512 * DM];
__device__ __nv_bfloat16 g_Chi[DM * NN];
__device__ __nv_bfloat16 g_Clo[DM * NN];
__device__ __nv_bfloat16 g_Dhi[(size_t)DM * DM];
__device__ __nv_bfloat16 g_Dlo[(size_t)DM * DM];

// ---------------------------------------------------------------------------
// PTX helpers (sm_80+ portable: cp.async / ldmatrix / mma.sync)
// ---------------------------------------------------------------------------
__device__ __forceinline__ uint32_t smem_u32(const void* p) {
    uint32_t a;
    asm("{ .reg .u64 t; cvta.to.shared.u64 t, %1; cvt.u32.u64 %0, t; }"
        : "=r"(a) : "l"(p));
    return a;
}

__device__ __forceinline__ void cp_async16(uint32_t saddr, const void* gaddr) {
    asm volatile("cp.async.cg.shared.global [%0], [%1], 16;"
                 :: "r"(saddr), "l"(gaddr));
}
#define CP_COMMIT() asm volatile("cp.async.commit_group;" ::: "memory")
#define CP_WAIT(N)  asm volatile("cp.async.wait_group %0;" :: "n"(N) : "memory")

__device__ __forceinline__ void ldm_x4(uint32_t* r, uint32_t addr) {
    asm volatile("ldmatrix.sync.aligned.m8n8.x4.shared.b16 {%0,%1,%2,%3}, [%4];"
                 : "=r"(r[0]), "=r"(r[1]), "=r"(r[2]), "=r"(r[3]) : "r"(addr));
}
__device__ __forceinline__ void ldm_x2(uint32_t* r, uint32_t addr) {
    asm volatile("ldmatrix.sync.aligned.m8n8.x2.shared.b16 {%0,%1}, [%2];"
                 : "=r"(r[0]), "=r"(r[1]) : "r"(addr));
}

__device__ __forceinline__ void mma_bf16(float* c, const uint32_t* a, const uint32_t* b) {
    asm volatile(
        "mma.sync.aligned.m16n8k16.row.col.f32.bf16.bf16.f32 "
        "{%0,%1,%2,%3}, {%4,%5,%6,%7}, {%8,%9}, {%0,%1,%2,%3};"
        : "+f"(c[0]), "+f"(c[1]), "+f"(c[2]), "+f"(c[3])
        : "r"(a[0]), "r"(a[1]), "r"(a[2]), "r"(a[3]), "r"(b[0]), "r"(b[1]));
}

// ---------------------------------------------------------------------------
// Split fp32 -> bf16 (hi, lo)
// ---------------------------------------------------------------------------
__global__ void __launch_bounds__(256)
split_kernel(const float* __restrict__ src, int sel, int n4)
{
    int i = blockIdx.x * blockDim.x + threadIdx.x;
    if (i >= n4) return;

    __nv_bfloat16 *hi, *lo;
    switch (sel) {
        case 0: hi = g_uhi;            lo = g_ulo;            break;
        case 1: hi = g_Whi;            lo = g_Wlo;            break;
        case 2: hi = g_Whi + 256 * DM; lo = g_Wlo + 256 * DM; break;
        case 3: hi = g_Chi;            lo = g_Clo;            break;
        default: hi = g_Dhi;           lo = g_Dlo;            break;
    }

    float4 v = reinterpret_cast<const float4*>(src)[i];
    __nv_bfloat16 h0 = __float2bfloat16(v.x);
    __nv_bfloat16 h1 = __float2bfloat16(v.y);
    __nv_bfloat16 h2 = __float2bfloat16(v.z);
    __nv_bfloat16 h3 = __float2bfloat16(v.w);
    ushort4 hv = make_ushort4(__bfloat16_as_ushort(h0), __bfloat16_as_ushort(h1),
                              __bfloat16_as_ushort(h2), __bfloat16_as_ushort(h3));
    ushort4 lv = make_ushort4(
        __bfloat16_as_ushort(__float2bfloat16(v.x - __bfloat162float(h0))),
        __bfloat16_as_ushort(__float2bfloat16(v.y - __bfloat162float(h1))),
        __bfloat16_as_ushort(__float2bfloat16(v.z - __bfloat162float(h2))),
        __bfloat16_as_ushort(__float2bfloat16(v.w - __bfloat162float(h3))));
    reinterpret_cast<ushort4*>(hi)[i] = hv;
    reinterpret_cast<ushort4*>(lo)[i] = lv;
}

// ---------------------------------------------------------------------------
// mma.sync split-bf16 GEMM. 128x128 CTA tile, 8 warps (2x4 -> 64x32 each),
// K-chunk 32, 3-stage cp.async pipeline.
// Smem stage layout (rows padded to 80B: conflict-free ldmatrix):
//   +0      A_hi (128 rows x 80B)
//   +10240  A_lo
//   +20480  B_hi
//   +30720  B_lo
// ---------------------------------------------------------------------------
#define ROW_B     80
#define TILE_B    (128 * ROW_B)      // 10240
#define STAGE_B   (4 * TILE_B)       // 40960
#define NSTAGE    3
#define SMEM_TOT  (NSTAGE * STAGE_B) // 122880

template <int MODE>   // 1: gemm1 (alpha/bu),  2: gemm2 (out)
__global__ void __launch_bounds__(256, 1)
gemm_mma(const float* __restrict__ bias_a, const float* __restrict__ bias_b,
         float* __restrict__ out)
{
    extern __shared__ __align__(128) char smem[];
    const uint32_t sb = smem_u32(smem);

    const int tid  = threadIdx.x;
    const int wid  = tid >> 5;
    const int lane = tid & 31;
    const int wm   = (wid >> 2) * 64;   // warp m offset in tile
    const int wn   = (wid & 3) * 32;    // warp n offset in tile

    const int bn = blockIdx.x * 128;    // N fastest -> A rows reused via L2
    const int bm = blockIdx.y * 128;

    const int NC = (MODE == 1) ? (DM / 32) : ((NN + DM) / 32);

    // ---- stage loader (cp.async) ----
    const int lrow = tid >> 2;          // 0..63  (x2 iterations -> 128 rows)
    const int lc16 = tid & 3;           // 16B chunk in row

    auto load_stage = [&](int chunk, int stg) {
        const __nv_bfloat16 *Ah, *Al, *Bh, *Bl;
        int lda, ldb, acol, bcol;
        if (MODE == 1) {
            Ah = g_uhi; Al = g_ulo; lda = DM; acol = chunk * 32;
            Bh = g_Whi; Bl = g_Wlo; ldb = DM; bcol = chunk * 32;
        } else {
            if (chunk < 8) {
                Ah = g_xhi; Al = g_xlo; lda = NN; acol = chunk * 32;
                Bh = g_Chi; Bl = g_Clo; ldb = NN; bcol = chunk * 32;
            } else {
                Ah = g_uhi; Al = g_ulo; lda = DM; acol = (chunk - 8) * 32;
                Bh = g_Dhi; Bl = g_Dlo; ldb = DM; bcol = (chunk - 8) * 32;
            }
        }
        const uint32_t st = sb + stg * STAGE_B;
        #pragma unroll
        for (int it = 0; it < 2; it++) {
            const int row = lrow + it * 64;
            const uint32_t so = (uint32_t)(row * ROW_B + lc16 * 16);
            const size_t ai = (size_t)(bm + row) * lda + acol + lc16 * 8;
            const size_t bi = (size_t)(bn + row) * ldb + bcol + lc16 * 8;
            cp_async16(st + so,              Ah + ai);
            cp_async16(st + TILE_B + so,     Al + ai);
            cp_async16(st + 2 * TILE_B + so, Bh + bi);
            cp_async16(st + 3 * TILE_B + so, Bl + bi);
        }
        CP_COMMIT();
    };

    // ---- accumulators ----
    float acc[4][4][4];
    #pragma unroll
    for (int i = 0; i < 4; i++)
        #pragma unroll
        for (int j = 0; j < 4; j++)
            #pragma unroll
            for (int e = 0; e < 4; e++) acc[i][j][e] = 0.f;

    // ldmatrix lane address components
    const uint32_t a_off = (uint32_t)((lane & 15) * ROW_B + (lane >> 4) * 16);
    const uint32_t b_off = (uint32_t)((lane & 7) * ROW_B + ((lane >> 3) & 1) * 16);

    load_stage(0, 0);
    if (NC > 1) load_stage(1, 1);

    for (int c = 0; c < NC; c++) {
        if (c + 2 < NC) { load_stage(c + 2, (c + 2) % NSTAGE); CP_WAIT(2); }
        else if (c + 1 < NC) { CP_WAIT(1); }
        else { CP_WAIT(0); }
        __syncthreads();

        const uint32_t st  = sb + (c % NSTAGE) * STAGE_B;
        const uint32_t ahb = st + (uint32_t)(wm * ROW_B) + a_off;
        const uint32_t alb = ahb + TILE_B;
        const uint32_t bhb = st + 2 * TILE_B + (uint32_t)(wn * ROW_B) + b_off;
        const uint32_t blb = bhb + TILE_B;

        #pragma unroll
        for (int kk = 0; kk < 2; kk++) {        // two k16 steps per chunk
            const uint32_t ko = kk * 32;        // 16 bf16 = 32 bytes
            uint32_t ah[4][4], al[4][4], bh[4][2], bl[4][2];
            #pragma unroll
            for (int mi = 0; mi < 4; mi++) {
                ldm_x4(ah[mi], ahb + mi * (16 * ROW_B) + ko);
                ldm_x4(al[mi], alb + mi * (16 * ROW_B) + ko);
            }
            #pragma unroll
            for (int ni = 0; ni < 4; ni++) {
                ldm_x2(bh[ni], bhb + ni * (8 * ROW_B) + ko);
                ldm_x2(bl[ni], blb + ni * (8 * ROW_B) + ko);
            }
            #pragma unroll
            for (int mi = 0; mi < 4; mi++)
                #pragma unroll
                for (int ni = 0; ni < 4; ni++) {
                    mma_bf16(acc[mi][ni], ah[mi], bh[ni]);
                    mma_bf16(acc[mi][ni], al[mi], bh[ni]);
                    mma_bf16(acc[mi][ni], ah[mi], bl[ni]);
                }
        }
        __syncthreads();
    }

    // ---- epilogue ----
    const int mrow0 = bm + wm + (lane >> 2);
    const int ncol0 = bn + wn + (lane & 3) * 2;

    #pragma unroll
    for (int mi = 0; mi < 4; mi++) {
        #pragma unroll
        for (int ni = 0; ni < 4; ni++) {
            const int n0 = ncol0 + ni * 8;
            #pragma unroll
            for (int half = 0; half < 2; half++) {     // rows m, m+8
                const int m = mrow0 + mi * 16 + half * 8;
                float v0 = acc[mi][ni][half * 2 + 0];
                float v1 = acc[mi][ni][half * 2 + 1];
                if (MODE == 1) {
                    if (n0 < NN) {
                        v0 += __ldg(&bias_a[n0]);
                        v1 += __ldg(&bias_a[n0 + 1]);
                        v0 = 1.0f / (1.0f + __expf(-v0));
                        v1 = 1.0f / (1.0f + __expf(-v1));
                        g_alpha[(size_t)m * NN + n0]     = v0;
                        g_alpha[(size_t)m * NN + n0 + 1] = v1;
                    } else {
                        v0 += __ldg(&bias_b[n0 - NN]);
                        v1 += __ldg(&bias_b[n0 - NN + 1]);
                        g_bu[(size_t)m * NN + (n0 - NN)]     = v0;
                        g_bu[(size_t)m * NN + (n0 - NN) + 1] = v1;
                    }
                } else {
                    out[(size_t)m * DM + n0]     = v0;
                    out[(size_t)m * DM + n0 + 1] = v1;
                }
            }
        }
    }
}

// ---------------------------------------------------------------------------
// Sequential scan; 64 blocks x 32 threads; writes xs as bf16 (hi, lo).
// ---------------------------------------------------------------------------
__global__ void __launch_bounds__(32)
scan_kernel()
{
    const int b = blockIdx.x;
    const int n = blockIdx.y * 32 + threadIdx.x;
    const size_t base = (size_t)b * SS * NN + n;
    const float* A  = g_alpha + base;
    const float* Bv = g_bu + base;
    __nv_bfloat16* Xh = g_xhi + base;
    __nv_bfloat16* Xl = g_xlo + base;

    const int PF = 16;
    float a0[PF], b0[PF];
    #pragma unroll
    for (int i = 0; i < PF; i++) {
        a0[i] = A[(size_t)i * NN];
        b0[i] = Bv[(size_t)i * NN];
    }

    float x = 0.0f;
    for (int s0 = 0; s0 < SS; s0 += PF) {
        float a1[PF], b1[PF];
        const int nxt = s0 + PF;
        if (nxt < SS) {
            #pragma unroll
            for (int i = 0; i < PF; i++) {
                a1[i] = A[(size_t)(nxt + i) * NN];
                b1[i] = Bv[(size_t)(nxt + i) * NN];
            }
        } else {
            #pragma unroll
            for (int i = 0; i < PF; i++) { a1[i] = 0.f; b1[i] = 0.f; }
        }
        #pragma unroll
        for (int i = 0; i < PF; i++) {
            x = fmaf(a0[i], x, b0[i]);
            __nv_bfloat16 h = __float2bfloat16(x);
            Xh[(size_t)(s0 + i) * NN] = h;
            Xl[(size_t)(s0 + i) * NN] = __float2bfloat16(x - __bfloat162float(h));
        }
        #pragma unroll
        for (int i = 0; i < PF; i++) { a0[i] = a1[i]; b0[i] = b1[i]; }
    }
}

// ---------------------------------------------------------------------------
extern "C" void kernel_launch(void* const* d_in, const int* in_sizes, int n_in,
                              void* d_out, int out_size)
{
    const float* u  = (const float*)d_in[0];
    const float* Wa = (const float*)d_in[1];
    const float* ba = (const float*)d_in[2];
    const float* Wb = (const float*)d_in[3];
    const float* bb = (const float*)d_in[4];
    const float* C  = (const float*)d_in[5];
    const float* Dm = (const float*)d_in[6];
    float* out = (float*)d_out;

    (void)cudaFuncSetAttribute(gemm_mma<1>,
        cudaFuncAttributeMaxDynamicSharedMemorySize, SMEM_TOT);
    (void)cudaFuncSetAttribute(gemm_mma<2>,
        cudaFuncAttributeMaxDynamicSharedMemorySize, SMEM_TOT);

    {
        int n4 = (int)((size_t)MM * DM / 4);
        split_kernel<<<(n4 + 255) / 256, 256>>>(u, 0, n4);
    }
    {
        int n4 = 256 * DM / 4;
        split_kernel<<<(n4 + 255) / 256, 256>>>(Wa, 1, n4);
        split_kernel<<<(n4 + 255) / 256, 256>>>(Wb, 2, n4);
        split_kernel<<<(DM * NN / 4 + 255) / 256, 256>>>(C, 3, DM * NN / 4);
    }
    {
        int n4 = DM * DM / 4;
        split_kernel<<<(n4 + 255) / 256, 256>>>(Dm, 4, n4);
    }

    // GEMM1: alpha / Bu   (M=32768, N=512, K=1024)
    gemm_mma<1><<<dim3(4, MM / 128), 256, SMEM_TOT>>>(ba, bb, nullptr);

    // scan (64 blocks x 32 threads)
    scan_kernel<<<dim3(BB, NN / 32), 32>>>();

    // GEMM2: y = [xs|u] . [C|Dm]^T   (M=32768, N=1024, K=1280)
    gemm_mma<2><<<dim3(DM / 128, MM / 128), 256, SMEM_TOT>>>(nullptr, nullptr, out);
}

// round 8
// speedup vs baseline: 3.4414x; 1.4332x over previous
#include <cuda_runtime.h>
#include <cuda_fp16.h>
#include <cstdint>

#define BB 8
#define SS 4096
#define DM 1024
#define NN 256
#define MM (BB*SS)   // 32768

// ---------------------------------------------------------------------------
// Scratch (device globals; allocation is forbidden)
// ---------------------------------------------------------------------------
__device__ float g_alpha[(size_t)MM * NN];
__device__ float g_bu[(size_t)MM * NN];
__device__ __half g_uhi[(size_t)MM * DM];
__device__ __half g_ulo[(size_t)MM * DM];
__device__ __half g_xhi[(size_t)MM * NN];
__device__ __half g_xlo[(size_t)MM * NN];
__device__ __half g_W[512 * DM];          // [Wa; Wb] fp16
__device__ __half g_C[DM * NN];           // C fp16
__device__ __half g_D[(size_t)DM * DM];   // Dm fp16

// ---------------------------------------------------------------------------
// PTX helpers (sm_80+ portable: cp.async / ldmatrix / mma.sync)
// ---------------------------------------------------------------------------
__device__ __forceinline__ uint32_t smem_u32(const void* p) {
    uint32_t a;
    asm("{ .reg .u64 t; cvta.to.shared.u64 t, %1; cvt.u32.u64 %0, t; }"
        : "=r"(a) : "l"(p));
    return a;
}

__device__ __forceinline__ void cp_async16(uint32_t saddr, const void* gaddr) {
    asm volatile("cp.async.cg.shared.global [%0], [%1], 16;"
                 :: "r"(saddr), "l"(gaddr));
}
#define CP_COMMIT() asm volatile("cp.async.commit_group;" ::: "memory")
#define CP_WAIT(N)  asm volatile("cp.async.wait_group %0;" :: "n"(N) : "memory")

__device__ __forceinline__ void ldm_x4(uint32_t* r, uint32_t addr) {
    asm volatile("ldmatrix.sync.aligned.m8n8.x4.shared.b16 {%0,%1,%2,%3}, [%4];"
                 : "=r"(r[0]), "=r"(r[1]), "=r"(r[2]), "=r"(r[3]) : "r"(addr));
}
__device__ __forceinline__ void ldm_x2(uint32_t* r, uint32_t addr) {
    asm volatile("ldmatrix.sync.aligned.m8n8.x2.shared.b16 {%0,%1}, [%2];"
                 : "=r"(r[0]), "=r"(r[1]) : "r"(addr));
}

__device__ __forceinline__ void mma_f16(float* c, const uint32_t* a, const uint32_t* b) {
    asm volatile(
        "mma.sync.aligned.m16n8k16.row.col.f32.f16.f16.f32 "
        "{%0,%1,%2,%3}, {%4,%5,%6,%7}, {%8,%9}, {%0,%1,%2,%3};"
        : "+f"(c[0]), "+f"(c[1]), "+f"(c[2]), "+f"(c[3])
        : "r"(a[0]), "r"(a[1]), "r"(a[2]), "r"(a[3]), "r"(b[0]), "r"(b[1]));
}

// ---------------------------------------------------------------------------
// u: fp32 -> fp16 (hi, lo)
// ---------------------------------------------------------------------------
__global__ void __launch_bounds__(256)
split_u_kernel(const float* __restrict__ src, int n4)
{
    int i = blockIdx.x * blockDim.x + threadIdx.x;
    if (i >= n4) return;
    float4 v = reinterpret_cast<const float4*>(src)[i];
    __half h0 = __float2half(v.x);
    __half h1 = __float2half(v.y);
    __half h2 = __float2half(v.z);
    __half h3 = __float2half(v.w);
    ushort4 hv = make_ushort4(__half_as_ushort(h0), __half_as_ushort(h1),
                              __half_as_ushort(h2), __half_as_ushort(h3));
    ushort4 lv = make_ushort4(
        __half_as_ushort(__float2half(v.x - __half2float(h0))),
        __half_as_ushort(__float2half(v.y - __half2float(h1))),
        __half_as_ushort(__float2half(v.z - __half2float(h2))),
        __half_as_ushort(__float2half(v.w - __half2float(h3))));
    reinterpret_cast<ushort4*>(g_uhi)[i] = hv;
    reinterpret_cast<ushort4*>(g_ulo)[i] = lv;
}

// ---------------------------------------------------------------------------
// weights: fp32 -> single fp16
// ---------------------------------------------------------------------------
__global__ void __launch_bounds__(256)
convert_kernel(const float* __restrict__ src, int sel, int n4)
{
    int i = blockIdx.x * blockDim.x + threadIdx.x;
    if (i >= n4) return;
    __half* dst;
    switch (sel) {
        case 1: dst = g_W;            break;
        case 2: dst = g_W + 256 * DM; break;
        case 3: dst = g_C;            break;
        default: dst = g_D;           break;
    }
    float4 v = reinterpret_cast<const float4*>(src)[i];
    ushort4 hv = make_ushort4(
        __half_as_ushort(__float2half(v.x)), __half_as_ushort(__float2half(v.y)),
        __half_as_ushort(__float2half(v.z)), __half_as_ushort(__float2half(v.w)));
    reinterpret_cast<ushort4*>(dst)[i] = hv;
}

// ---------------------------------------------------------------------------
// mma.sync fp16 2-term GEMM. 128x128 CTA tile, 8 warps (2x4 -> 64x32 each),
// K-chunk 32, 4-stage cp.async pipeline.
// Stage layout (rows padded to 80B -> conflict-free ldmatrix):
//   +0      A_hi (128 x 80B)
//   +10240  A_lo
//   +20480  B
// ---------------------------------------------------------------------------
#define ROW_B     80
#define TILE_B    (128 * ROW_B)      // 10240
#define STAGE_B   (3 * TILE_B)       // 30720
#define NSTAGE    4
#define SMEM_TOT  (NSTAGE * STAGE_B) // 122880

template <int MODE>   // 1: gemm1 (alpha/bu),  2: gemm2 (out)
__global__ void __launch_bounds__(256, 1)
gemm_mma(const float* __restrict__ bias_a, const float* __restrict__ bias_b,
         float* __restrict__ out)
{
    extern __shared__ __align__(128) char smem[];
    const uint32_t sb = smem_u32(smem);

    const int tid  = threadIdx.x;
    const int wid  = tid >> 5;
    const int lane = tid & 31;
    const int wm   = (wid >> 2) * 64;
    const int wn   = (wid & 3) * 32;

    const int bn = blockIdx.x * 128;   // N fastest -> A rows reused via L2
    const int bm = blockIdx.y * 128;

    const int NC = (MODE == 1) ? (DM / 32) : ((NN + DM) / 32);

    const int lrow = tid >> 2;         // 0..63 (x2 -> 128 rows)
    const int lc16 = tid & 3;          // 16B chunk in 64B row

    auto load_stage = [&](int chunk, int stg) {
        const __half *Ah, *Al, *Bp;
        int lda, ldb, acol, bcol;
        if (MODE == 1) {
            Ah = g_uhi; Al = g_ulo; lda = DM; acol = chunk * 32;
            Bp = g_W;               ldb = DM; bcol = chunk * 32;
        } else {
            if (chunk < 8) {
                Ah = g_xhi; Al = g_xlo; lda = NN; acol = chunk * 32;
                Bp = g_C;               ldb = NN; bcol = chunk * 32;
            } else {
                Ah = g_uhi; Al = g_ulo; lda = DM; acol = (chunk - 8) * 32;
                Bp = g_D;               ldb = DM; bcol = (chunk - 8) * 32;
            }
        }
        const uint32_t st = sb + stg * STAGE_B;
        #pragma unroll
        for (int it = 0; it < 2; it++) {
            const int row = lrow + it * 64;
            const uint32_t so = (uint32_t)(row * ROW_B + lc16 * 16);
            const size_t ai = (size_t)(bm + row) * lda + acol + lc16 * 8;
            const size_t bi = (size_t)(bn + row) * ldb + bcol + lc16 * 8;
            cp_async16(st + so,              Ah + ai);
            cp_async16(st + TILE_B + so,     Al + ai);
            cp_async16(st + 2 * TILE_B + so, Bp + bi);
        }
        CP_COMMIT();
    };

    float acc[4][4][4];
    #pragma unroll
    for (int i = 0; i < 4; i++)
        #pragma unroll
        for (int j = 0; j < 4; j++)
            #pragma unroll
            for (int e = 0; e < 4; e++) acc[i][j][e] = 0.f;

    const uint32_t a_off = (uint32_t)((lane & 15) * ROW_B + (lane >> 4) * 16);
    const uint32_t b_off = (uint32_t)((lane & 7) * ROW_B + ((lane >> 3) & 1) * 16);

    load_stage(0, 0);
    load_stage(1, 1);
    load_stage(2, 2);

    for (int c = 0; c < NC; c++) {
        if (c + 2 < NC)      { CP_WAIT(2); }
        else if (c + 1 < NC) { CP_WAIT(1); }
        else                 { CP_WAIT(0); }
        __syncthreads();

        const uint32_t st  = sb + (c % NSTAGE) * STAGE_B;
        const uint32_t ahb = st + (uint32_t)(wm * ROW_B) + a_off;
        const uint32_t alb = ahb + TILE_B;
        const uint32_t bb_ = st + 2 * TILE_B + (uint32_t)(wn * ROW_B) + b_off;

        #pragma unroll
        for (int kk = 0; kk < 2; kk++) {
            const uint32_t ko = kk * 32;
            uint32_t ah[4][4], al[4][4], bf[4][2];
            #pragma unroll
            for (int mi = 0; mi < 4; mi++) {
                ldm_x4(ah[mi], ahb + mi * (16 * ROW_B) + ko);
                ldm_x4(al[mi], alb + mi * (16 * ROW_B) + ko);
            }
            #pragma unroll
            for (int ni = 0; ni < 4; ni++)
                ldm_x2(bf[ni], bb_ + ni * (8 * ROW_B) + ko);
            #pragma unroll
            for (int mi = 0; mi < 4; mi++)
                #pragma unroll
                for (int ni = 0; ni < 4; ni++) {
                    mma_f16(acc[mi][ni], ah[mi], bf[ni]);
                    mma_f16(acc[mi][ni], al[mi], bf[ni]);
                }
        }

        if (c + 3 < NC) load_stage(c + 3, (c + 3) % NSTAGE);
    }

    // ---- epilogue ----
    const int mrow0 = bm + wm + (lane >> 2);
    const int ncol0 = bn + wn + (lane & 3) * 2;

    #pragma unroll
    for (int mi = 0; mi < 4; mi++) {
        #pragma unroll
        for (int ni = 0; ni < 4; ni++) {
            const int n0 = ncol0 + ni * 8;
            #pragma unroll
            for (int half = 0; half < 2; half++) {
                const int m = mrow0 + mi * 16 + half * 8;
                float v0 = acc[mi][ni][half * 2 + 0];
                float v1 = acc[mi][ni][half * 2 + 1];
                if (MODE == 1) {
                    if (n0 < NN) {
                        v0 += __ldg(&bias_a[n0]);
                        v1 += __ldg(&bias_a[n0 + 1]);
                        v0 = 1.0f / (1.0f + __expf(-v0));
                        v1 = 1.0f / (1.0f + __expf(-v1));
                        g_alpha[(size_t)m * NN + n0]     = v0;
                        g_alpha[(size_t)m * NN + n0 + 1] = v1;
                    } else {
                        v0 += __ldg(&bias_b[n0 - NN]);
                        v1 += __ldg(&bias_b[n0 - NN + 1]);
                        g_bu[(size_t)m * NN + (n0 - NN)]     = v0;
                        g_bu[(size_t)m * NN + (n0 - NN) + 1] = v1;
                    }
                } else {
                    out[(size_t)m * DM + n0]     = v0;
                    out[(size_t)m * DM + n0 + 1] = v1;
                }
            }
        }
    }
}

// ---------------------------------------------------------------------------
// Sequential scan; 64 blocks x 32 threads; writes xs as fp16 (hi, lo).
// ---------------------------------------------------------------------------
__global__ void __launch_bounds__(32)
scan_kernel()
{
    const int b = blockIdx.x;
    const int n = blockIdx.y * 32 + threadIdx.x;
    const size_t base = (size_t)b * SS * NN + n;
    const float* A  = g_alpha + base;
    const float* Bv = g_bu + base;
    __half* Xh = g_xhi + base;
    __half* Xl = g_xlo + base;

    const int PF = 16;
    float a0[PF], b0[PF];
    #pragma unroll
    for (int i = 0; i < PF; i++) {
        a0[i] = A[(size_t)i * NN];
        b0[i] = Bv[(size_t)i * NN];
    }

    float x = 0.0f;
    for (int s0 = 0; s0 < SS; s0 += PF) {
        float a1[PF], b1[PF];
        const int nxt = s0 + PF;
        if (nxt < SS) {
            #pragma unroll
            for (int i = 0; i < PF; i++) {
                a1[i] = A[(size_t)(nxt + i) * NN];
                b1[i] = Bv[(size_t)(nxt + i) * NN];
            }
        } else {
            #pragma unroll
            for (int i = 0; i < PF; i++) { a1[i] = 0.f; b1[i] = 0.f; }
        }
        #pragma unroll
        for (int i = 0; i < PF; i++) {
            x = fmaf(a0[i], x, b0[i]);
            __half h = __float2half(x);
            Xh[(size_t)(s0 + i) * NN] = h;
            Xl[(size_t)(s0 + i) * NN] = __float2half(x - __half2float(h));
        }
        #pragma unroll
        for (int i = 0; i < PF; i++) { a0[i] = a1[i]; b0[i] = b1[i]; }
    }
}

// ---------------------------------------------------------------------------
extern "C" void kernel_launch(void* const* d_in, const int* in_sizes, int n_in,
                              void* d_out, int out_size)
{
    const float* u  = (const float*)d_in[0];
    const float* Wa = (const float*)d_in[1];
    const float* ba = (const float*)d_in[2];
    const float* Wb = (const float*)d_in[3];
    const float* bb = (const float*)d_in[4];
    const float* C  = (const float*)d_in[5];
    const float* Dm = (const float*)d_in[6];
    float* out = (float*)d_out;

    (void)cudaFuncSetAttribute(gemm_mma<1>,
        cudaFuncAttributeMaxDynamicSharedMemorySize, SMEM_TOT);
    (void)cudaFuncSetAttribute(gemm_mma<2>,
        cudaFuncAttributeMaxDynamicSharedMemorySize, SMEM_TOT);

    {
        int n4 = (int)((size_t)MM * DM / 4);
        split_u_kernel<<<(n4 + 255) / 256, 256>>>(u, n4);
    }
    {
        int n4 = 256 * DM / 4;
        convert_kernel<<<(n4 + 255) / 256, 256>>>(Wa, 1, n4);
        convert_kernel<<<(n4 + 255) / 256, 256>>>(Wb, 2, n4);
        convert_kernel<<<(DM * NN / 4 + 255) / 256, 256>>>(C, 3, DM * NN / 4);
        convert_kernel<<<(DM * DM / 4 + 255) / 256, 256>>>(Dm, 4, DM * DM / 4);
    }

    // GEMM1: alpha / Bu   (M=32768, N=512, K=1024)
    gemm_mma<1><<<dim3(4, MM / 128), 256, SMEM_TOT>>>(ba, bb, nullptr);

    // scan (64 blocks x 32 threads)
    scan_kernel<<<dim3(BB, NN / 32), 32>>>();

    // GEMM2: y = [xs|u] . [C|Dm]^T   (M=32768, N=1024, K=1280)
    gemm_mma<2><<<dim3(DM / 128, MM / 128), 256, SMEM_TOT>>>(nullptr, nullptr, out);
}